// round 3
// baseline (speedup 1.0000x reference)
#include <cuda_runtime.h>

// OrdLoss: sum over valid voxels of [k<=t]*log(clip(p)) + [k>t]*log(clip(1-p)),
// divided by -count(valid). pred [N,C,D,H,W] f32, target replicated over C
// (read channel 0 only), mask [N,1,D,H,W] i32.
//
// Key transforms vs naive:
//  * q = (k<=t)? p : 1-p  lies in (0,1], so clip-max never binds; clip-min
//    via one FMAX.
//  * sum of 4 logs -> log of product-of-4 (product >= 1e-32 > FLT_MIN, safe):
//    4 logf per voxel instead of 16.
//  * loads front-batched 8x float4 per phase for high MLP.
//  * single kernel, last-block-done final reduction (deterministic order).

#define N_      2
#define C_      16
#define MSP     (32 * 128 * 128)      // 524288 voxels per batch item
#define NVOX    (N_ * MSP)            // 1048576
#define NGROUPS (NVOX / 4)            // 262144 float4 groups
#define BLOCKS  1024
#define THREADS 256
// BLOCKS*THREADS == NGROUPS exactly

__device__ float g_partial[BLOCKS];
__device__ int   g_count[BLOCKS];
__device__ unsigned int g_ticket = 0;

__global__ void __launch_bounds__(THREADS, 4)
ord_loss_fused(const float* __restrict__ pred,
               const int*   __restrict__ target,
               const int*   __restrict__ mask,
               float*       __restrict__ out)
{
    const int g = blockIdx.x * THREADS + threadIdx.x;  // group of 4 voxels
    const int m = g * 4;
    const int n = m >> 19;                              // MSP == 2^19
    const int base = m + n * (C_ - 1) * MSP;            // n*C*MSP + spatial

    const int4 mk = *reinterpret_cast<const int4*>(mask + m);
    const int4 tg = *reinterpret_cast<const int4*>(target + base);

    int   t[4] = { tg.x, tg.y, tg.z, tg.w };
    float acc[4] = { 0.0f, 0.0f, 0.0f, 0.0f };

#pragma unroll
    for (int b = 0; b < 2; ++b) {
        // ---- front-batch 8 channel loads (MLP_p1 = 8) ----
        float4 P[8];
#pragma unroll
        for (int j = 0; j < 8; ++j)
            P[j] = *reinterpret_cast<const float4*>(pred + base + (b * 8 + j) * MSP);

        const float* Pf = reinterpret_cast<const float*>(P);  // P[j] elem v -> Pf[j*4+v]

#pragma unroll
        for (int v = 0; v < 4; ++v) {
            float pa = 1.0f, pb = 1.0f;
#pragma unroll
            for (int j = 0; j < 4; ++j) {
                const int   k = b * 8 + j;
                const float p = Pf[j * 4 + v];
                const float q = (k <= t[v]) ? p : (1.0f - p);
                pa *= fmaxf(q, 1e-8f);
            }
#pragma unroll
            for (int j = 4; j < 8; ++j) {
                const int   k = b * 8 + j;
                const float p = Pf[j * 4 + v];
                const float q = (k <= t[v]) ? p : (1.0f - p);
                pb *= fmaxf(q, 1e-8f);
            }
            acc[v] += __logf(pa) + __logf(pb);
        }
    }

    const float a_thread =
        ((mk.x > 0) ? acc[0] : 0.0f) + ((mk.y > 0) ? acc[1] : 0.0f) +
        ((mk.z > 0) ? acc[2] : 0.0f) + ((mk.w > 0) ? acc[3] : 0.0f);
    int cnt = (mk.x > 0) + (mk.y > 0) + (mk.z > 0) + (mk.w > 0);
    float a = a_thread;

    // ---- warp reduce ----
#pragma unroll
    for (int off = 16; off > 0; off >>= 1) {
        a   += __shfl_xor_sync(0xFFFFFFFFu, a, off);
        cnt += __shfl_xor_sync(0xFFFFFFFFu, cnt, off);
    }

    __shared__ float sa[THREADS / 32];
    __shared__ int   sc[THREADS / 32];
    __shared__ bool  s_last;
    const int wid = threadIdx.x >> 5;
    const int lid = threadIdx.x & 31;
    if (lid == 0) { sa[wid] = a; sc[wid] = cnt; }
    __syncthreads();

    if (threadIdx.x == 0) {
        float aa = sa[0] + sa[1] + sa[2] + sa[3] + sa[4] + sa[5] + sa[6] + sa[7];
        int   cc = sc[0] + sc[1] + sc[2] + sc[3] + sc[4] + sc[5] + sc[6] + sc[7];
        g_partial[blockIdx.x] = aa;
        g_count[blockIdx.x]   = cc;
        __threadfence();
        unsigned int old = atomicAdd(&g_ticket, 1u);
        s_last = (old == BLOCKS - 1);
    }
    __syncthreads();

    if (!s_last) return;

    // ---- last block: final reduction over 1024 partials, fixed order ----
    float s = 0.0f;
    int   c = 0;
#pragma unroll
    for (int i = 0; i < BLOCKS / THREADS; ++i) {
        const int idx = threadIdx.x + i * THREADS;
        s += g_partial[idx];
        c += g_count[idx];
    }
#pragma unroll
    for (int off = 16; off > 0; off >>= 1) {
        s += __shfl_xor_sync(0xFFFFFFFFu, s, off);
        c += __shfl_xor_sync(0xFFFFFFFFu, c, off);
    }
    __shared__ float fa[THREADS / 32];
    __shared__ int   fc[THREADS / 32];
    if (lid == 0) { fa[wid] = s; fc[wid] = c; }
    __syncthreads();
    if (threadIdx.x == 0) {
        float ss = fa[0] + fa[1] + fa[2] + fa[3] + fa[4] + fa[5] + fa[6] + fa[7];
        int   cc = fc[0] + fc[1] + fc[2] + fc[3] + fc[4] + fc[5] + fc[6] + fc[7];
        out[0] = -ss / (float)cc;
        g_ticket = 0;   // reset for next graph replay
    }
}

extern "C" void kernel_launch(void* const* d_in, const int* in_sizes, int n_in,
                              void* d_out, int out_size)
{
    const float* pred   = (const float*)d_in[0];
    const int*   target = (const int*)d_in[1];
    const int*   mask   = (const int*)d_in[2];
    float*       out    = (float*)d_out;

    ord_loss_fused<<<BLOCKS, THREADS>>>(pred, target, mask, out);
}

// round 4
// speedup vs baseline: 1.0290x; 1.0290x over previous
#include <cuda_runtime.h>

// OrdLoss: sum over valid voxels of [k<=t]*log(clip(p)) + [k>t]*log(clip(1-p)),
// divided by -count(valid). pred [N,C,D,H,W] f32, target replicated over C
// (read channel 0 only), mask [N,1,D,H,W] i32.
//
//  * q = (k<=t)? p : 1-p  in (0,1]: clip-max never binds; clip-min = one FMAX.
//  * log-fusion: running product of 4 channels per voxel, one __logf per
//    flush (4 logs/voxel instead of 16). prod >= 1e-32 > FLT_MIN: safe.
//  * NO explicit load staging (R3 regression: regs 64, occ 40%) — lean
//    interleaved loop, ptxas schedules the 16 independent LDG.128s.
//  * single kernel, last-block-done final reduction (deterministic order).

#define N_      2
#define C_      16
#define MSP     (32 * 128 * 128)      // 524288 voxels per batch item
#define NVOX    (N_ * MSP)            // 1048576
#define NGROUPS (NVOX / 4)            // 262144 float4 groups
#define BLOCKS  1024
#define THREADS 256
// BLOCKS*THREADS == NGROUPS exactly

__device__ float g_partial[BLOCKS];
__device__ int   g_count[BLOCKS];
__device__ unsigned int g_ticket = 0;

__global__ void __launch_bounds__(THREADS)
ord_loss_fused(const float* __restrict__ pred,
               const int*   __restrict__ target,
               const int*   __restrict__ mask,
               float*       __restrict__ out)
{
    const int g = blockIdx.x * THREADS + threadIdx.x;  // group of 4 voxels
    const int m = g * 4;
    const int n = m >> 19;                              // MSP == 2^19
    const int base = m + n * (C_ - 1) * MSP;            // n*C*MSP + spatial

    const int4 mk = *reinterpret_cast<const int4*>(mask + m);
    const int4 tg = *reinterpret_cast<const int4*>(target + base);

    float prod0 = 1.0f, prod1 = 1.0f, prod2 = 1.0f, prod3 = 1.0f;
    float acc0 = 0.0f, acc1 = 0.0f, acc2 = 0.0f, acc3 = 0.0f;

#pragma unroll
    for (int k = 0; k < C_; ++k) {
        const float4 p = *reinterpret_cast<const float4*>(pred + base + k * MSP);
        prod0 *= fmaxf((k <= tg.x) ? p.x : (1.0f - p.x), 1e-8f);
        prod1 *= fmaxf((k <= tg.y) ? p.y : (1.0f - p.y), 1e-8f);
        prod2 *= fmaxf((k <= tg.z) ? p.z : (1.0f - p.z), 1e-8f);
        prod3 *= fmaxf((k <= tg.w) ? p.w : (1.0f - p.w), 1e-8f);
        if ((k & 3) == 3) {            // flush every 4 channels (no underflow)
            acc0 += __logf(prod0); prod0 = 1.0f;
            acc1 += __logf(prod1); prod1 = 1.0f;
            acc2 += __logf(prod2); prod2 = 1.0f;
            acc3 += __logf(prod3); prod3 = 1.0f;
        }
    }

    float a =
        ((mk.x > 0) ? acc0 : 0.0f) + ((mk.y > 0) ? acc1 : 0.0f) +
        ((mk.z > 0) ? acc2 : 0.0f) + ((mk.w > 0) ? acc3 : 0.0f);
    int cnt = (mk.x > 0) + (mk.y > 0) + (mk.z > 0) + (mk.w > 0);

    // ---- warp reduce ----
#pragma unroll
    for (int off = 16; off > 0; off >>= 1) {
        a   += __shfl_xor_sync(0xFFFFFFFFu, a, off);
        cnt += __shfl_xor_sync(0xFFFFFFFFu, cnt, off);
    }

    __shared__ float sa[THREADS / 32];
    __shared__ int   sc[THREADS / 32];
    __shared__ bool  s_last;
    const int wid = threadIdx.x >> 5;
    const int lid = threadIdx.x & 31;
    if (lid == 0) { sa[wid] = a; sc[wid] = cnt; }
    __syncthreads();

    if (threadIdx.x == 0) {
        float aa = sa[0] + sa[1] + sa[2] + sa[3] + sa[4] + sa[5] + sa[6] + sa[7];
        int   cc = sc[0] + sc[1] + sc[2] + sc[3] + sc[4] + sc[5] + sc[6] + sc[7];
        g_partial[blockIdx.x] = aa;
        g_count[blockIdx.x]   = cc;
        __threadfence();
        unsigned int old = atomicAdd(&g_ticket, 1u);
        s_last = (old == BLOCKS - 1);
    }
    __syncthreads();

    if (!s_last) return;

    // ---- last block: final reduction over 1024 partials, fixed order ----
    float s = 0.0f;
    int   c = 0;
#pragma unroll
    for (int i = 0; i < BLOCKS / THREADS; ++i) {
        const int idx = threadIdx.x + i * THREADS;
        s += g_partial[idx];
        c += g_count[idx];
    }
#pragma unroll
    for (int off = 16; off > 0; off >>= 1) {
        s += __shfl_xor_sync(0xFFFFFFFFu, s, off);
        c += __shfl_xor_sync(0xFFFFFFFFu, c, off);
    }
    __shared__ float fa[THREADS / 32];
    __shared__ int   fc[THREADS / 32];
    if (lid == 0) { fa[wid] = s; fc[wid] = c; }
    __syncthreads();
    if (threadIdx.x == 0) {
        float ss = fa[0] + fa[1] + fa[2] + fa[3] + fa[4] + fa[5] + fa[6] + fa[7];
        int   cc = fc[0] + fc[1] + fc[2] + fc[3] + fc[4] + fc[5] + fc[6] + fc[7];
        out[0] = -ss / (float)cc;
        g_ticket = 0;   // reset for next graph replay
    }
}

extern "C" void kernel_launch(void* const* d_in, const int* in_sizes, int n_in,
                              void* d_out, int out_size)
{
    const float* pred   = (const float*)d_in[0];
    const int*   target = (const int*)d_in[1];
    const int*   mask   = (const int*)d_in[2];
    float*       out    = (float*)d_out;

    ord_loss_fused<<<BLOCKS, THREADS>>>(pred, target, mask, out);
}

// round 5
// speedup vs baseline: 1.1379x; 1.1059x over previous
#include <cuda_runtime.h>

// OrdLoss: sum over valid voxels of [k<=t]*log(clip(p)) + [k>t]*log(clip(1-p)),
// divided by -count(valid). pred [N,C,D,H,W] f32, target replicated over C
// (read channel 0 only), mask [N,1,D,H,W] i32.
//
//  * q = (k<=t)? p : 1-p  lies in (0,1]: clip-max never binds.
//  * mask folded into clip bound: c_v = valid ? 1e-8 : 1.0, so
//    fmax(q, c_v) = 1.0 for invalid voxels -> log contributes 0. Exact.
//  * product across the 4 voxels of each channel (>= 1e-32, no underflow),
//    ONE __logf per channel, ONE accumulator -> minimal register state.
//  * __launch_bounds__(256, 8): <=32 regs, 8 blocks/SM, grid 1024 fully
//    resident -> single wave, 2x bytes-in-flight (R4 was 1.73 ragged waves).
//  * single kernel, last-block-done final reduction (deterministic order).

#define N_      2
#define C_      16
#define MSP     (32 * 128 * 128)      // 524288 voxels per batch item
#define NVOX    (N_ * MSP)            // 1048576
#define NGROUPS (NVOX / 4)            // 262144 float4 groups
#define BLOCKS  1024
#define THREADS 256
// BLOCKS*THREADS == NGROUPS exactly

__device__ float g_partial[BLOCKS];
__device__ int   g_count[BLOCKS];
__device__ unsigned int g_ticket = 0;

__global__ void __launch_bounds__(THREADS, 8)
ord_loss_fused(const float* __restrict__ pred,
               const int*   __restrict__ target,
               const int*   __restrict__ mask,
               float*       __restrict__ out)
{
    const int g = blockIdx.x * THREADS + threadIdx.x;  // group of 4 voxels
    const int m = g * 4;
    const int n = m >> 19;                              // MSP == 2^19
    const int base = m + n * (C_ - 1) * MSP;            // n*C*MSP + spatial

    const int4 mk = *reinterpret_cast<const int4*>(mask + m);
    const int4 tg = *reinterpret_cast<const int4*>(target + base);

    // mask folded into per-voxel clip floor: invalid -> floor 1.0 -> q'=1 -> log 0
    const float c0 = (mk.x > 0) ? 1e-8f : 1.0f;
    const float c1 = (mk.y > 0) ? 1e-8f : 1.0f;
    const float c2 = (mk.z > 0) ? 1e-8f : 1.0f;
    const float c3 = (mk.w > 0) ? 1e-8f : 1.0f;
    int cnt = (mk.x > 0) + (mk.y > 0) + (mk.z > 0) + (mk.w > 0);

    float acc = 0.0f;

#pragma unroll
    for (int k = 0; k < C_; ++k) {
        const float4 p = *reinterpret_cast<const float4*>(pred + base + k * MSP);
        const float q0 = fmaxf((k <= tg.x) ? p.x : (1.0f - p.x), c0);
        const float q1 = fmaxf((k <= tg.y) ? p.y : (1.0f - p.y), c1);
        const float q2 = fmaxf((k <= tg.z) ? p.z : (1.0f - p.z), c2);
        const float q3 = fmaxf((k <= tg.w) ? p.w : (1.0f - p.w), c3);
        acc += __logf((q0 * q1) * (q2 * q3));   // product >= 1e-32, safe
    }

    float a = acc;

    // ---- warp reduce ----
#pragma unroll
    for (int off = 16; off > 0; off >>= 1) {
        a   += __shfl_xor_sync(0xFFFFFFFFu, a, off);
        cnt += __shfl_xor_sync(0xFFFFFFFFu, cnt, off);
    }

    __shared__ float sa[THREADS / 32];
    __shared__ int   sc[THREADS / 32];
    __shared__ bool  s_last;
    const int wid = threadIdx.x >> 5;
    const int lid = threadIdx.x & 31;
    if (lid == 0) { sa[wid] = a; sc[wid] = cnt; }
    __syncthreads();

    if (threadIdx.x == 0) {
        float aa = sa[0] + sa[1] + sa[2] + sa[3] + sa[4] + sa[5] + sa[6] + sa[7];
        int   cc = sc[0] + sc[1] + sc[2] + sc[3] + sc[4] + sc[5] + sc[6] + sc[7];
        g_partial[blockIdx.x] = aa;
        g_count[blockIdx.x]   = cc;
        __threadfence();
        unsigned int old = atomicAdd(&g_ticket, 1u);
        s_last = (old == BLOCKS - 1);
    }
    __syncthreads();

    if (!s_last) return;

    // ---- last block: final reduction over 1024 partials, fixed order ----
    float s = 0.0f;
    int   c = 0;
#pragma unroll
    for (int i = 0; i < BLOCKS / THREADS; ++i) {
        const int idx = threadIdx.x + i * THREADS;
        s += g_partial[idx];
        c += g_count[idx];
    }
#pragma unroll
    for (int off = 16; off > 0; off >>= 1) {
        s += __shfl_xor_sync(0xFFFFFFFFu, s, off);
        c += __shfl_xor_sync(0xFFFFFFFFu, c, off);
    }
    __shared__ float fa[THREADS / 32];
    __shared__ int   fc[THREADS / 32];
    if (lid == 0) { fa[wid] = s; fc[wid] = c; }
    __syncthreads();
    if (threadIdx.x == 0) {
        float ss = fa[0] + fa[1] + fa[2] + fa[3] + fa[4] + fa[5] + fa[6] + fa[7];
        int   cc = fc[0] + fc[1] + fc[2] + fc[3] + fc[4] + fc[5] + fc[6] + fc[7];
        out[0] = -ss / (float)cc;
        g_ticket = 0;   // reset for next graph replay
    }
}

extern "C" void kernel_launch(void* const* d_in, const int* in_sizes, int n_in,
                              void* d_out, int out_size)
{
    const float* pred   = (const float*)d_in[0];
    const int*   target = (const int*)d_in[1];
    const int*   mask   = (const int*)d_in[2];
    float*       out    = (float*)d_out;

    ord_loss_fused<<<BLOCKS, THREADS>>>(pred, target, mask, out);
}